// round 2
// baseline (speedup 1.0000x reference)
#include <cuda_runtime.h>

// PolyConvFrame: Jacobi polynomial graph convolution.
#define N_NODE   100000
#define N_EDGE   1600000
#define D_FEAT   64
#define DEPTH    10
#define LSTRIDE  ((DEPTH + 1) * D_FEAT)   // 704 floats per node in output

// -------- device scratch (no allocation allowed) --------
__device__ int   g_deg[N_NODE];
__device__ int   g_rowptr[N_NODE + 1];
__device__ int   g_slot[N_NODE];
__device__ float g_dinv[N_NODE];
__device__ int   g_cols[N_EDGE];
__device__ float g_vals[N_EDGE];
__device__ float g_coef[(DEPTH + 1) * 4];   // per level: {cS, cX1, cX2, pad}
__device__ int   g_idx64;                   // 1 if edge_index is int64, 0 if int32

// -------- 0. detect edge_index dtype (int64 vs int32) --------
// int64 little-endian nonneg < 2^31  => every odd int32 word is 0.
// Real int32 index data (random 0..99999) => sampled odd words ~never all zero.
__global__ void detect_kernel(const int* __restrict__ ei32) {
    if (threadIdx.x != 0 || blockIdx.x != 0) return;
    int is64 = 1;
    const long long total32 = 2LL * N_EDGE * 2;   // if it were int64, buffer has this many int32 words
    for (int k = 0; k < 256; k++) {
        long long pos = ((long long)k * (total32 / 256)) | 1;   // odd position
        if (pos >= 2LL * N_EDGE) break;  // if actually int32, stay in bounds of 3.2M words
        if (ei32[pos] != 0) { is64 = 0; break; }
    }
    g_idx64 = is64;
}

__device__ __forceinline__ int load_idx(const void* ei, long long pos, int is64) {
    return is64 ? (int)((const long long*)ei)[pos] : ((const int*)ei)[pos];
}

// -------- 1. zero counters --------
__global__ void zero_kernel() {
    int i = blockIdx.x * blockDim.x + threadIdx.x;
    if (i < N_NODE) { g_deg[i] = 0; g_slot[i] = 0; }
}

// -------- 2. out-degree histogram --------
__global__ void count_kernel(const void* __restrict__ ei) {
    int e = blockIdx.x * blockDim.x + threadIdx.x;
    if (e >= N_EDGE) return;
    int is64 = g_idx64;
    int r = load_idx(ei, e, is64);
    if ((unsigned)r < N_NODE) atomicAdd(&g_deg[r], 1);
}

// -------- 3. exclusive scan -> rowptr, and dinv --------
__global__ void scan_kernel() {
    __shared__ int partial[1024];
    int tid = threadIdx.x;
    const int chunk = (N_NODE + 1023) / 1024;
    int beg = tid * chunk;
    int end = beg + chunk; if (end > N_NODE) end = N_NODE;
    int s = 0;
    if (beg < N_NODE)
        for (int i = beg; i < end; i++) s += g_deg[i];
    partial[tid] = s;
    __syncthreads();
    for (int off = 1; off < 1024; off <<= 1) {
        int v = (tid >= off) ? partial[tid - off] : 0;
        __syncthreads();
        partial[tid] += v;
        __syncthreads();
    }
    int run = (tid == 0) ? 0 : partial[tid - 1];
    if (beg < N_NODE) {
        for (int i = beg; i < end; i++) {
            g_rowptr[i] = run;
            int d = g_deg[i];
            run += d;
            g_dinv[i] = rsqrtf((float)(d == 0 ? 1 : d));   // deg<0.5 -> deg+1
        }
    }
    if (tid == 0) g_rowptr[N_NODE] = partial[1023];
}

// -------- 4. scatter edges into CSR with normalized values --------
__global__ void scatter_kernel(const void* __restrict__ ei,
                               const float* __restrict__ edge_attr) {
    int e = blockIdx.x * blockDim.x + threadIdx.x;
    if (e >= N_EDGE) return;
    int is64 = g_idx64;
    int r = load_idx(ei, e, is64);
    int c = load_idx(ei, (long long)e + N_EDGE, is64);
    if ((unsigned)r >= N_NODE || (unsigned)c >= N_NODE) return;
    int pos = g_rowptr[r] + atomicAdd(&g_slot[r], 1);
    g_cols[pos] = c;
    g_vals[pos] = g_dinv[r] * edge_attr[e] * g_dinv[c];
}

// -------- 5. per-level recurrence coefficients (depend on alpha input) --------
__global__ void coef_kernel(const float* __restrict__ alpha_params) {
    if (threadIdx.x != 0 || blockIdx.x != 0) return;
    const float BASEALPHA = 1.0f;
    const float a = 1.0f, b = 1.0f, l = -1.0f, r = 1.0f;
    float alphas[DEPTH + 1];
    for (int i = 0; i <= DEPTH; i++) alphas[i] = BASEALPHA * tanhf(alpha_params[i]);

    float coef1 = (a - b) * 0.5f - (a + b + 2.0f) * 0.5f * (l + r) / (r - l);
    float coef2 = (a + b + 2.0f) / (r - l);
    g_coef[1 * 4 + 0] = alphas[0] * coef2;
    g_coef[1 * 4 + 1] = alphas[0] * coef1;
    g_coef[1 * 4 + 2] = 0.0f;

    for (int L = 2; L <= DEPTH; L++) {
        float Lf = (float)L;
        float coef_l     = 2.0f * Lf * (Lf + a + b) * (2.0f * Lf - 2.0f + a + b);
        float coef_lm1_1 = (2.0f * Lf + a + b - 1.0f) * (2.0f * Lf + a + b) * (2.0f * Lf + a + b - 2.0f);
        float coef_lm1_2 = (2.0f * Lf + a + b - 1.0f) * (a * a - b * b);
        float coef_lm2   = 2.0f * (Lf - 1.0f + a) * (Lf - 1.0f + b) * (2.0f * Lf + a + b);
        float tmp1 = alphas[L - 1] * (coef_lm1_1 / coef_l);
        float tmp2 = alphas[L - 1] * (coef_lm1_2 / coef_l);
        float tmp3 = alphas[L - 1] * alphas[L - 2] * (coef_lm2 / coef_l);
        float tmp1_2 = tmp1 * (2.0f / (r - l));
        float tmp2_2 = tmp1 * ((r + l) / (r - l)) + tmp2;
        g_coef[L * 4 + 0] = tmp1_2;
        g_coef[L * 4 + 1] = -tmp2_2;
        g_coef[L * 4 + 2] = -tmp3;
    }
}

// -------- 6. level 0: copy x into out slice 0 --------
__global__ void copy0_kernel(const float4* __restrict__ x, float4* __restrict__ out) {
    int i = blockIdx.x * blockDim.x + threadIdx.x;
    const int NV = N_NODE * (D_FEAT / 4);
    if (i >= NV) return;
    int n = i >> 4;
    int d4 = i & 15;
    out[(size_t)n * (LSTRIDE / 4) + d4] = x[i];
}

// -------- 7. fused SpMM + recurrence, one warp per node --------
__global__ __launch_bounds__(256) void level_kernel(float* __restrict__ out, int L) {
    int w = (blockIdx.x * blockDim.x + threadIdx.x) >> 5;
    if (w >= N_NODE) return;
    int lane = threadIdx.x & 31;

    float cS = g_coef[L * 4 + 0];
    float c1 = g_coef[L * 4 + 1];
    float c2 = g_coef[L * 4 + 2];

    const int ycol = (L - 1) * D_FEAT + lane * 2;
    int start = g_rowptr[w];
    int end   = g_rowptr[w + 1];

    float ax = 0.0f, ay = 0.0f;
    int e = start;
    for (; e + 4 <= end; e += 4) {
        int   i0 = g_cols[e],     i1 = g_cols[e + 1], i2 = g_cols[e + 2], i3 = g_cols[e + 3];
        float v0 = g_vals[e],     v1 = g_vals[e + 1], v2 = g_vals[e + 2], v3 = g_vals[e + 3];
        float2 y0 = *(const float2*)(out + (size_t)i0 * LSTRIDE + ycol);
        float2 y1 = *(const float2*)(out + (size_t)i1 * LSTRIDE + ycol);
        float2 y2 = *(const float2*)(out + (size_t)i2 * LSTRIDE + ycol);
        float2 y3 = *(const float2*)(out + (size_t)i3 * LSTRIDE + ycol);
        ax += v0 * y0.x; ay += v0 * y0.y;
        ax += v1 * y1.x; ay += v1 * y1.y;
        ax += v2 * y2.x; ay += v2 * y2.y;
        ax += v3 * y3.x; ay += v3 * y3.y;
    }
    for (; e < end; e++) {
        int   c = g_cols[e];
        float v = g_vals[e];
        float2 y = *(const float2*)(out + (size_t)c * LSTRIDE + ycol);
        ax += v * y.x; ay += v * y.y;
    }

    int Lm2 = (L >= 2) ? (L - 2) : 0;   // for L==1, c2==0 so the read is harmless
    float* row = out + (size_t)w * LSTRIDE;
    float2 x1 = *(const float2*)(row + (L - 1) * D_FEAT + lane * 2);
    float2 x2 = *(const float2*)(row + Lm2 * D_FEAT + lane * 2);
    float2 res;
    res.x = cS * ax + c1 * x1.x + c2 * x2.x;
    res.y = cS * ay + c1 * x1.y + c2 * x2.y;
    *(float2*)(row + L * D_FEAT + lane * 2) = res;
}

extern "C" void kernel_launch(void* const* d_in, const int* in_sizes, int n_in,
                              void* d_out, int out_size) {
    const float* x            = (const float*)d_in[0];
    const float* edge_attr    = (const float*)d_in[1];
    const float* alpha_params = (const float*)d_in[2];
    const void*  edge_index   = d_in[3];
    float* out = (float*)d_out;

    (void)in_sizes; (void)n_in; (void)out_size;

    const int T = 256;
    detect_kernel <<<1, 32>>>((const int*)edge_index);
    zero_kernel   <<<(N_NODE + T - 1) / T, T>>>();
    count_kernel  <<<(N_EDGE + T - 1) / T, T>>>(edge_index);
    scan_kernel   <<<1, 1024>>>();
    scatter_kernel<<<(N_EDGE + T - 1) / T, T>>>(edge_index, edge_attr);
    coef_kernel   <<<1, 32>>>(alpha_params);

    const int NV = N_NODE * (D_FEAT / 4);
    copy0_kernel  <<<(NV + T - 1) / T, T>>>((const float4*)x, (float4*)out);

    const int warps_grid = (N_NODE * 32 + T - 1) / T;
    for (int L = 1; L <= DEPTH; L++)
        level_kernel<<<warps_grid, T>>>(out, L);
}

// round 3
// speedup vs baseline: 1.1995x; 1.1995x over previous
#include <cuda_runtime.h>
#include <cuda_fp16.h>

// PolyConvFrame: Jacobi polynomial graph convolution.
#define N_NODE   100000
#define N_EDGE   1600000
#define D_FEAT   64
#define DEPTH    10
#define LSTRIDE  ((DEPTH + 1) * D_FEAT)   // 704 floats per node in output
#define SCAN_BS  1024
#define NBLK     ((N_NODE + SCAN_BS - 1) / SCAN_BS)   // 98

// -------- device scratch (no allocation allowed) --------
__device__ int    g_deg[N_NODE];
__device__ int    g_rowptr[N_NODE + 1];
__device__ int    g_slot[N_NODE];
__device__ float  g_dinv[N_NODE];
__device__ int    g_cols[N_EDGE];
__device__ float  g_vals[N_EDGE];
__device__ float  g_coef[(DEPTH + 1) * 4];
__device__ int    g_idx64;
__device__ int    g_blocksum[NBLK];
__device__ int    g_blockoff[NBLK];
__device__ __half g_xh[2 * N_NODE * D_FEAT];   // fp16 ping-pong mirror of last level

// -------- 0. detect edge_index dtype (int64 vs int32), warp-parallel --------
__global__ void detect_kernel(const int* __restrict__ ei32) {
    int lane = threadIdx.x;
    const long long total32 = 2LL * N_EDGE * 2;
    int nonzero = 0;
    for (int k = lane; k < 256; k += 32) {
        long long pos = ((long long)k * (total32 / 256)) | 1;   // odd word = high half if int64
        if (pos < 2LL * N_EDGE && ei32[pos] != 0) nonzero = 1;  // stay in int32 bounds
    }
    unsigned any = __ballot_sync(0xFFFFFFFFu, nonzero);
    if (lane == 0) g_idx64 = (any == 0u) ? 1 : 0;
}

__device__ __forceinline__ int load_idx(const void* ei, long long pos, int is64) {
    return is64 ? (int)((const long long*)ei)[pos] : ((const int*)ei)[pos];
}

// -------- 1. zero counters --------
__global__ void zero_kernel() {
    int i = blockIdx.x * blockDim.x + threadIdx.x;
    if (i < N_NODE) { g_deg[i] = 0; g_slot[i] = 0; }
}

// -------- 2. out-degree histogram --------
__global__ void count_kernel(const void* __restrict__ ei) {
    int e = blockIdx.x * blockDim.x + threadIdx.x;
    if (e >= N_EDGE) return;
    int r = load_idx(ei, e, g_idx64);
    if ((unsigned)r < N_NODE) atomicAdd(&g_deg[r], 1);
}

// -------- 3a. per-block inclusive scan -> local exclusive prefix + block sum --------
__global__ void scan_a_kernel() {
    __shared__ int sh[SCAN_BS];
    int tid = threadIdx.x;
    int i = blockIdx.x * SCAN_BS + tid;
    int s = (i < N_NODE) ? g_deg[i] : 0;
    sh[tid] = s;
    __syncthreads();
    for (int off = 1; off < SCAN_BS; off <<= 1) {
        int v = (tid >= off) ? sh[tid - off] : 0;
        __syncthreads();
        sh[tid] += v;
        __syncthreads();
    }
    if (i < N_NODE) g_rowptr[i] = sh[tid] - s;     // local exclusive
    if (tid == SCAN_BS - 1) g_blocksum[blockIdx.x] = sh[tid];
}

// -------- 3b. scan the 98 block sums --------
__global__ void scan_b_kernel() {
    __shared__ int sh[128];
    int tid = threadIdx.x;
    int s = (tid < NBLK) ? g_blocksum[tid] : 0;
    sh[tid] = s;
    __syncthreads();
    for (int off = 1; off < 128; off <<= 1) {
        int v = (tid >= off) ? sh[tid - off] : 0;
        __syncthreads();
        sh[tid] += v;
        __syncthreads();
    }
    if (tid < NBLK) g_blockoff[tid] = sh[tid] - s;
    if (tid == 127) g_rowptr[N_NODE] = sh[127];    // total = N_EDGE (all indices valid)
}

// -------- 3c. add block offsets + compute dinv --------
__global__ void scan_c_kernel() {
    int i = blockIdx.x * blockDim.x + threadIdx.x;
    if (i >= N_NODE) return;
    g_rowptr[i] += g_blockoff[i >> 10];
    int d = g_deg[i];
    g_dinv[i] = rsqrtf((float)(d == 0 ? 1 : d));   // deg<0.5 -> deg+1
}

// -------- 4. scatter edges into CSR with normalized values --------
__global__ void scatter_kernel(const void* __restrict__ ei,
                               const float* __restrict__ edge_attr) {
    int e = blockIdx.x * blockDim.x + threadIdx.x;
    if (e >= N_EDGE) return;
    int is64 = g_idx64;
    int r = load_idx(ei, e, is64);
    int c = load_idx(ei, (long long)e + N_EDGE, is64);
    if ((unsigned)r >= N_NODE || (unsigned)c >= N_NODE) return;
    int pos = g_rowptr[r] + atomicAdd(&g_slot[r], 1);
    g_cols[pos] = c;
    g_vals[pos] = g_dinv[r] * edge_attr[e] * g_dinv[c];
}

// -------- 5. per-level recurrence coefficients --------
__global__ void coef_kernel(const float* __restrict__ alpha_params) {
    if (threadIdx.x != 0 || blockIdx.x != 0) return;
    const float BASEALPHA = 1.0f;
    const float a = 1.0f, b = 1.0f, l = -1.0f, r = 1.0f;
    float alphas[DEPTH + 1];
    for (int i = 0; i <= DEPTH; i++) alphas[i] = BASEALPHA * tanhf(alpha_params[i]);

    float coef1 = (a - b) * 0.5f - (a + b + 2.0f) * 0.5f * (l + r) / (r - l);
    float coef2 = (a + b + 2.0f) / (r - l);
    g_coef[1 * 4 + 0] = alphas[0] * coef2;
    g_coef[1 * 4 + 1] = alphas[0] * coef1;
    g_coef[1 * 4 + 2] = 0.0f;

    for (int L = 2; L <= DEPTH; L++) {
        float Lf = (float)L;
        float coef_l     = 2.0f * Lf * (Lf + a + b) * (2.0f * Lf - 2.0f + a + b);
        float coef_lm1_1 = (2.0f * Lf + a + b - 1.0f) * (2.0f * Lf + a + b) * (2.0f * Lf + a + b - 2.0f);
        float coef_lm1_2 = (2.0f * Lf + a + b - 1.0f) * (a * a - b * b);
        float coef_lm2   = 2.0f * (Lf - 1.0f + a) * (Lf - 1.0f + b) * (2.0f * Lf + a + b);
        float tmp1 = alphas[L - 1] * (coef_lm1_1 / coef_l);
        float tmp2 = alphas[L - 1] * (coef_lm1_2 / coef_l);
        float tmp3 = alphas[L - 1] * alphas[L - 2] * (coef_lm2 / coef_l);
        float tmp1_2 = tmp1 * (2.0f / (r - l));
        float tmp2_2 = tmp1 * ((r + l) / (r - l)) + tmp2;
        g_coef[L * 4 + 0] = tmp1_2;
        g_coef[L * 4 + 1] = -tmp2_2;
        g_coef[L * 4 + 2] = -tmp3;
    }
}

// -------- 6. level 0: copy x into out slice 0 + fp16 mirror buf 0 --------
__global__ void copy0_kernel(const float2* __restrict__ x, float* __restrict__ out) {
    int i = blockIdx.x * blockDim.x + threadIdx.x;       // over N_NODE * 32 float2s
    const int NV = N_NODE * (D_FEAT / 2);
    if (i >= NV) return;
    int n = i >> 5;
    int d2 = i & 31;
    float2 v = x[i];
    *(float2*)(out + (size_t)n * LSTRIDE + d2 * 2) = v;
    *(__half2*)(g_xh + (size_t)n * D_FEAT + d2 * 2) = __float22half2_rn(v);
}

// -------- 7. fused SpMM (fp16 gather) + recurrence, one warp per node --------
__global__ __launch_bounds__(256) void level_kernel(float* __restrict__ out, int L) {
    int w = (blockIdx.x * blockDim.x + threadIdx.x) >> 5;
    if (w >= N_NODE) return;
    int lane = threadIdx.x & 31;

    float cS = g_coef[L * 4 + 0];
    float c1 = g_coef[L * 4 + 1];
    float c2 = g_coef[L * 4 + 2];

    const __half* ysrc = g_xh + (size_t)((L - 1) & 1) * (N_NODE * D_FEAT);
    __half*       ydst = g_xh + (size_t)(L & 1)       * (N_NODE * D_FEAT);
    const int off = lane * 2;

    int start = g_rowptr[w];
    int end   = g_rowptr[w + 1];

    float ax = 0.0f, ay = 0.0f;
    int e = start;
    for (; e + 4 <= end; e += 4) {
        int   i0 = g_cols[e],  i1 = g_cols[e + 1], i2 = g_cols[e + 2], i3 = g_cols[e + 3];
        float v0 = g_vals[e],  v1 = g_vals[e + 1], v2 = g_vals[e + 2], v3 = g_vals[e + 3];
        float2 y0 = __half22float2(*(const __half2*)(ysrc + (size_t)i0 * D_FEAT + off));
        float2 y1 = __half22float2(*(const __half2*)(ysrc + (size_t)i1 * D_FEAT + off));
        float2 y2 = __half22float2(*(const __half2*)(ysrc + (size_t)i2 * D_FEAT + off));
        float2 y3 = __half22float2(*(const __half2*)(ysrc + (size_t)i3 * D_FEAT + off));
        ax += v0 * y0.x; ay += v0 * y0.y;
        ax += v1 * y1.x; ay += v1 * y1.y;
        ax += v2 * y2.x; ay += v2 * y2.y;
        ax += v3 * y3.x; ay += v3 * y3.y;
    }
    for (; e < end; e++) {
        int   c = g_cols[e];
        float v = g_vals[e];
        float2 y = __half22float2(*(const __half2*)(ysrc + (size_t)c * D_FEAT + off));
        ax += v * y.x; ay += v * y.y;
    }

    int Lm2 = (L >= 2) ? (L - 2) : 0;    // for L==1, c2==0 so the read is harmless
    float* row = out + (size_t)w * LSTRIDE;
    float2 x1 = *(const float2*)(row + (L - 1) * D_FEAT + off);
    float2 x2 = *(const float2*)(row + Lm2 * D_FEAT + off);
    float2 res;
    res.x = cS * ax + c1 * x1.x + c2 * x2.x;
    res.y = cS * ay + c1 * x1.y + c2 * x2.y;
    *(float2*)(row + L * D_FEAT + off) = res;
    *(__half2*)(ydst + (size_t)w * D_FEAT + off) = __float22half2_rn(res);
}

extern "C" void kernel_launch(void* const* d_in, const int* in_sizes, int n_in,
                              void* d_out, int out_size) {
    const float* x            = (const float*)d_in[0];
    const float* edge_attr    = (const float*)d_in[1];
    const float* alpha_params = (const float*)d_in[2];
    const void*  edge_index   = d_in[3];
    float* out = (float*)d_out;

    (void)in_sizes; (void)n_in; (void)out_size;

    const int T = 256;
    detect_kernel <<<1, 32>>>((const int*)edge_index);
    zero_kernel   <<<(N_NODE + T - 1) / T, T>>>();
    count_kernel  <<<(N_EDGE + T - 1) / T, T>>>(edge_index);
    scan_a_kernel <<<NBLK, SCAN_BS>>>();
    scan_b_kernel <<<1, 128>>>();
    scan_c_kernel <<<(N_NODE + T - 1) / T, T>>>();
    scatter_kernel<<<(N_EDGE + T - 1) / T, T>>>(edge_index, edge_attr);
    coef_kernel   <<<1, 32>>>(alpha_params);

    const int NV2 = N_NODE * (D_FEAT / 2);
    copy0_kernel  <<<(NV2 + T - 1) / T, T>>>((const float2*)x, out);

    const int warps_grid = (N_NODE * 32 + T - 1) / T;
    for (int L = 1; L <= DEPTH; L++)
        level_kernel<<<warps_grid, T>>>(out, L);
}